// round 1
// baseline (speedup 1.0000x reference)
#include <cuda_runtime.h>
#include <cuda_bf16.h>
#include <cstdint>

// Problem constants (fixed shapes for this problem)
#define B_   32
#define M_   512
#define S_   10
#define V_   32000
#define D_   128
#define HOPS_ 3

// Scratch: bag-sums for tables 1..3 (table 0's bag is fused into logits0).
// 3 * 32 * 512 * 128 floats = 25.2 MB
__device__ __align__(16) float g_bag[3u * B_ * M_ * D_];
__device__ float g_logits0[B_ * M_];

__device__ __forceinline__ float warpSum(float v) {
    #pragma unroll
    for (int o = 16; o > 0; o >>= 1) v += __shfl_xor_sync(0xffffffffu, v, o);
    return v;
}
__device__ __forceinline__ float warpMax(float v) {
    #pragma unroll
    for (int o = 16; o > 0; o >>= 1) v = fmaxf(v, __shfl_xor_sync(0xffffffffu, v, o));
    return v;
}

// ---------------------------------------------------------------------------
// Phase 1: one warp per (b, m). Read the 10 tokens once, gather-sum rows from
// all 4 tables. Table 0 -> dot with hidden (logits0). Tables 1..3 -> g_bag.
// Each lane owns one float4 (4 of the 128 dims).
// ---------------------------------------------------------------------------
__global__ void __launch_bounds__(256) k_gather(const int* __restrict__ story,
                                                const float* __restrict__ hidden,
                                                const float* __restrict__ C)
{
    const int warp = (blockIdx.x * blockDim.x + threadIdx.x) >> 5;
    const int lane = threadIdx.x & 31;
    if (warp >= B_ * M_) return;
    const int b = warp / M_;
    const int m = warp % M_;

    int tok = 0;
    if (lane < S_) tok = story[(b * M_ + m) * S_ + lane];

    float4 a0 = make_float4(0.f, 0.f, 0.f, 0.f);
    float4 a1 = a0, a2 = a0, a3 = a0;

    const float4* C4 = reinterpret_cast<const float4*>(C);
    const size_t rows_per_tab = (size_t)V_ * (D_ / 4);   // in float4 units

    #pragma unroll
    for (int s = 0; s < S_; s++) {
        const int t = __shfl_sync(0xffffffffu, tok, s);
        const size_t base = (size_t)t * (D_ / 4) + lane;
        float4 r0 = C4[base];
        float4 r1 = C4[base + rows_per_tab];
        float4 r2 = C4[base + 2 * rows_per_tab];
        float4 r3 = C4[base + 3 * rows_per_tab];
        a0.x += r0.x; a0.y += r0.y; a0.z += r0.z; a0.w += r0.w;
        a1.x += r1.x; a1.y += r1.y; a1.z += r1.z; a1.w += r1.w;
        a2.x += r2.x; a2.y += r2.y; a2.z += r2.z; a2.w += r2.w;
        a3.x += r3.x; a3.y += r3.y; a3.z += r3.z; a3.w += r3.w;
    }

    // logits0[b,m] = dot(bag_table0[b,m,:], hidden[b,:])
    const float4 u4 = reinterpret_cast<const float4*>(hidden + (size_t)b * D_)[lane];
    float d = a0.x * u4.x + a0.y * u4.y + a0.z * u4.z + a0.w * u4.w;
    d = warpSum(d);
    if (lane == 0) g_logits0[b * M_ + m] = d;

    // store bags for tables 1..3
    float4* bag4 = reinterpret_cast<float4*>(g_bag);
    const size_t row = ((size_t)b * M_ + m) * (D_ / 4) + lane;
    const size_t tabstride = (size_t)B_ * M_ * (D_ / 4);
    bag4[row]                 = a1;
    bag4[row + tabstride]     = a2;
    bag4[row + 2 * tabstride] = a3;
}

// ---------------------------------------------------------------------------
// Phase 2: one block per batch element. Runs all 3 hops:
//   softmax(logits) -> o = sum_m prob[m]*bag[h][b,m,:] -> u += o
//   -> next logits = dot(bag[h][b,m,:], u)
// g_bag table index h corresponds to reference table C[h+1].
// Final prob_logit is the logits computed entering hop 2 (pre-softmax).
// ---------------------------------------------------------------------------
__global__ void __launch_bounds__(512) k_hops(const float* __restrict__ hidden,
                                              float* __restrict__ out)
{
    __shared__ __align__(16) float s_u[D_];
    __shared__ float s_logit[M_];
    __shared__ float s_prob[M_];
    __shared__ __align__(16) float s_osc[16][D_];
    __shared__ float s_red[16];

    const int b    = blockIdx.x;
    const int tid  = threadIdx.x;          // 0..511
    const int lane = tid & 31;
    const int wid  = tid >> 5;             // 0..15

    if (tid < D_) s_u[tid] = hidden[(size_t)b * D_ + tid];
    s_logit[tid] = g_logits0[b * M_ + tid];   // M_ == blockDim == 512
    __syncthreads();

    const float4* bagbase = reinterpret_cast<const float4*>(g_bag);
    const size_t tabstride = (size_t)B_ * M_ * (D_ / 4);

    for (int h = 0; h < HOPS_; h++) {
        // ---- softmax over s_logit[0..511] ----
        float l = s_logit[tid];
        float wmx = warpMax(l);
        if (lane == 0) s_red[wid] = wmx;
        __syncthreads();
        float mx = s_red[0];
        #pragma unroll
        for (int i = 1; i < 16; i++) mx = fmaxf(mx, s_red[i]);
        float e = __expf(l - mx);
        __syncthreads();                       // done reading s_red
        float wsm = warpSum(e);
        if (lane == 0) s_red[wid] = wsm;
        __syncthreads();
        float ssum = 0.f;
        #pragma unroll
        for (int i = 0; i < 16; i++) ssum += s_red[i];
        s_prob[tid] = e * __frcp_rn(ssum);
        __syncthreads();

        // ---- o[d] = sum_m prob[m] * bag[h][b,m,d]; u += o ----
        const float4* bagp = bagbase + (size_t)h * tabstride
                                     + (size_t)b * M_ * (D_ / 4);
        const int d4 = tid & 31;               // float4 index in row
        const int g  = tid >> 5;               // 16 m-groups
        float4 acc = make_float4(0.f, 0.f, 0.f, 0.f);
        #pragma unroll 4
        for (int m = g; m < M_; m += 16) {
            const float p = s_prob[m];
            const float4 v = bagp[(size_t)m * 32 + d4];
            acc.x += p * v.x; acc.y += p * v.y;
            acc.z += p * v.z; acc.w += p * v.w;
        }
        reinterpret_cast<float4*>(&s_osc[g][0])[d4] = acc;
        __syncthreads();
        if (tid < D_) {
            float o = 0.f;
            #pragma unroll
            for (int i = 0; i < 16; i++) o += s_osc[i][tid];
            s_u[tid] += o;
        }
        __syncthreads();

        // ---- next logits (for hop h+1): dot(bag[h][b,m,:], u) ----
        if (h < HOPS_ - 1) {
            const float4 uu = reinterpret_cast<const float4*>(s_u)[lane];
            #pragma unroll 4
            for (int m = wid; m < M_; m += 16) {
                const float4 v = bagp[(size_t)m * 32 + lane];
                float dd = v.x * uu.x + v.y * uu.y + v.z * uu.z + v.w * uu.w;
                dd = warpSum(dd);
                if (lane == 0) s_logit[m] = dd;
            }
            __syncthreads();
            if (h == HOPS_ - 2) {
                // logits entering the final hop == reference prob_logit output
                out[(size_t)b * M_ + tid] = s_logit[tid];
            }
        }
    }

    if (tid < D_) out[(size_t)B_ * M_ + (size_t)b * D_ + tid] = s_u[tid];
}

extern "C" void kernel_launch(void* const* d_in, const int* in_sizes, int n_in,
                              void* d_out, int out_size)
{
    const int*   story  = (const int*)  d_in[0];   // [B, M, S] int32
    const float* hidden = (const float*)d_in[1];   // [B, 1, D] f32
    const float* C      = (const float*)d_in[2];   // [4, V, D] f32
    float* out = (float*)d_out;                    // [B*M] logits ++ [B*D] u

    // Phase 1: one warp per (b,m) -> 16384 warps, 8 warps/block
    k_gather<<<(B_ * M_) / 8, 256>>>(story, hidden, C);
    // Phase 2: one block per batch
    k_hops<<<B_, 512>>>(hidden, out);
}

// round 2
// speedup vs baseline: 1.3711x; 1.3711x over previous
#include <cuda_runtime.h>
#include <cuda_bf16.h>
#include <cstdint>

#define B_    32
#define M_    512
#define S_    10
#define V_    32000
#define D_    128
#define HOPS_ 3
#define NSPL  16          // m-splits per batch in phase 2 -> grid 512

// Scratch (device globals; zero-initialized at module load)
__device__ __align__(16) float g_bag[3u * B_ * M_ * D_];   // bags for tables 1..3
__device__ float g_logits[B_ * M_];                        // current hop logits
__device__ __align__(16) float g_part[B_ * NSPL * D_];     // partial o per split
__device__ __align__(16) float g_u[B_ * D_];               // running query u
__device__ unsigned int g_cnt[B_];                         // arrival counters (self-resetting)

__device__ __forceinline__ float warpSum(float v) {
    #pragma unroll
    for (int o = 16; o > 0; o >>= 1) v += __shfl_xor_sync(0xffffffffu, v, o);
    return v;
}
__device__ __forceinline__ float warpMax(float v) {
    #pragma unroll
    for (int o = 16; o > 0; o >>= 1) v = fmaxf(v, __shfl_xor_sync(0xffffffffu, v, o));
    return v;
}

// ---------------------------------------------------------------------------
// Phase 1: one warp per (b, m). Gather-sum rows from all 4 tables.
// Table 0 -> dot with hidden (hop-0 logits). Tables 1..3 -> g_bag.
// ---------------------------------------------------------------------------
__global__ void __launch_bounds__(256) k_gather(const int* __restrict__ story,
                                                const float* __restrict__ hidden,
                                                const float* __restrict__ C)
{
    const int warp = (blockIdx.x * blockDim.x + threadIdx.x) >> 5;
    const int lane = threadIdx.x & 31;
    if (warp >= B_ * M_) return;
    const int b = warp / M_;
    const int m = warp % M_;

    int tok = 0;
    if (lane < S_) tok = story[(b * M_ + m) * S_ + lane];

    float4 a0 = make_float4(0.f, 0.f, 0.f, 0.f);
    float4 a1 = a0, a2 = a0, a3 = a0;

    const float4* C4 = reinterpret_cast<const float4*>(C);
    const size_t rows_per_tab = (size_t)V_ * (D_ / 4);

    #pragma unroll
    for (int s = 0; s < S_; s++) {
        const int t = __shfl_sync(0xffffffffu, tok, s);
        const size_t base = (size_t)t * (D_ / 4) + lane;
        float4 r0 = C4[base];
        float4 r1 = C4[base + rows_per_tab];
        float4 r2 = C4[base + 2 * rows_per_tab];
        float4 r3 = C4[base + 3 * rows_per_tab];
        a0.x += r0.x; a0.y += r0.y; a0.z += r0.z; a0.w += r0.w;
        a1.x += r1.x; a1.y += r1.y; a1.z += r1.z; a1.w += r1.w;
        a2.x += r2.x; a2.y += r2.y; a2.z += r2.z; a2.w += r2.w;
        a3.x += r3.x; a3.y += r3.y; a3.z += r3.z; a3.w += r3.w;
    }

    // hop-0 logits
    const float4 u4 = reinterpret_cast<const float4*>(hidden + (size_t)b * D_)[lane];
    float d = a0.x * u4.x + a0.y * u4.y + a0.z * u4.z + a0.w * u4.w;
    d = warpSum(d);
    if (lane == 0) g_logits[b * M_ + m] = d;

    float4* bag4 = reinterpret_cast<float4*>(g_bag);
    const size_t row = ((size_t)b * M_ + m) * (D_ / 4) + lane;
    const size_t tabstride = (size_t)B_ * M_ * (D_ / 4);
    bag4[row]                 = a1;
    bag4[row + tabstride]     = a2;
    bag4[row + 2 * tabstride] = a3;
}

// ---------------------------------------------------------------------------
// Phase 2a: softmax + weighted combine, parallel over (b, m-slice).
// grid = B*NSPL. Each block: redundant softmax of g_logits[b], partial
// o over its 32-m slice, last block per batch reduces partials -> g_u.
// hop==2: last block also writes final u to out.
// ---------------------------------------------------------------------------
__global__ void __launch_bounds__(256) k_combine(const float* __restrict__ hidden,
                                                 float* __restrict__ out,
                                                 int hop)
{
    __shared__ float s_prob[M_];
    __shared__ float s_red[8];
    __shared__ __align__(16) float s_part[8][D_];
    __shared__ int s_last;

    const int b   = blockIdx.x / NSPL;
    const int sp  = blockIdx.x % NSPL;
    const int tid = threadIdx.x;
    const int lane = tid & 31;
    const int wid  = tid >> 5;            // 0..7

    // ---- softmax over g_logits[b][0..511] (redundant per block; cheap) ----
    const float l0 = g_logits[b * M_ + tid];
    const float l1 = g_logits[b * M_ + tid + 256];
    float wm = warpMax(fmaxf(l0, l1));
    if (lane == 0) s_red[wid] = wm;
    __syncthreads();
    float mx = s_red[0];
    #pragma unroll
    for (int i = 1; i < 8; i++) mx = fmaxf(mx, s_red[i]);
    const float e0 = __expf(l0 - mx);
    const float e1 = __expf(l1 - mx);
    __syncthreads();
    float ws = warpSum(e0 + e1);
    if (lane == 0) s_red[wid] = ws;
    __syncthreads();
    float ssum = 0.f;
    #pragma unroll
    for (int i = 0; i < 8; i++) ssum += s_red[i];
    const float inv = __frcp_rn(ssum);
    s_prob[tid]       = e0 * inv;
    s_prob[tid + 256] = e1 * inv;
    __syncthreads();

    // ---- partial o over m-slice [sp*32, sp*32+32) ----
    const size_t tabstride = (size_t)B_ * M_ * (D_ / 4);
    const float4* bagp = reinterpret_cast<const float4*>(g_bag)
                       + (size_t)hop * tabstride + (size_t)b * M_ * (D_ / 4);
    const int m0 = sp * 32;
    float4 acc = make_float4(0.f, 0.f, 0.f, 0.f);
    #pragma unroll
    for (int i = 0; i < 4; i++) {
        const int m = m0 + wid + 8 * i;
        const float p = s_prob[m];
        const float4 v = bagp[(size_t)m * 32 + lane];
        acc.x += p * v.x; acc.y += p * v.y;
        acc.z += p * v.z; acc.w += p * v.w;
    }
    reinterpret_cast<float4*>(&s_part[wid][0])[lane] = acc;
    __syncthreads();
    if (tid < D_) {
        float v = 0.f;
        #pragma unroll
        for (int g = 0; g < 8; g++) v += s_part[g][tid];
        g_part[((size_t)b * NSPL + sp) * D_ + tid] = v;
    }
    __syncthreads();

    // ---- last-block-per-batch deterministic reduction ----
    if (tid == 0) {
        __threadfence();
        const unsigned old = atomicAdd(&g_cnt[b], 1u);
        s_last = (old == NSPL - 1);
    }
    __syncthreads();
    if (s_last) {
        if (tid < D_) {
            float u = (hop == 0) ? hidden[(size_t)b * D_ + tid]
                                 : g_u[(size_t)b * D_ + tid];
            #pragma unroll
            for (int s2 = 0; s2 < NSPL; s2++)
                u += g_part[((size_t)b * NSPL + s2) * D_ + tid];
            g_u[(size_t)b * D_ + tid] = u;
            if (hop == HOPS_ - 1)
                out[(size_t)B_ * M_ + (size_t)b * D_ + tid] = u;
        }
        __threadfence();
        if (tid == 0) g_cnt[b] = 0;   // reset for next hop / next replay
    }
}

// ---------------------------------------------------------------------------
// Phase 2b: next logits: logit[m] = dot(bag[hop][b,m,:], u[b]).
// grid = B*NSPL, 8 warps/block, 4 m per warp.
// write_out != 0: also write logits to the output buffer (final prob_logit).
// ---------------------------------------------------------------------------
__global__ void __launch_bounds__(256) k_logits(float* __restrict__ out,
                                                int hop, int write_out)
{
    const int b   = blockIdx.x / NSPL;
    const int sp  = blockIdx.x % NSPL;
    const int tid = threadIdx.x;
    const int lane = tid & 31;
    const int wid  = tid >> 5;

    const float4 u4 = reinterpret_cast<const float4*>(g_u + (size_t)b * D_)[lane];

    const size_t tabstride = (size_t)B_ * M_ * (D_ / 4);
    const float4* bagp = reinterpret_cast<const float4*>(g_bag)
                       + (size_t)hop * tabstride + (size_t)b * M_ * (D_ / 4);
    const int m0 = sp * 32;
    #pragma unroll
    for (int i = 0; i < 4; i++) {
        const int m = m0 + wid + 8 * i;
        const float4 v = bagp[(size_t)m * 32 + lane];
        float d = v.x * u4.x + v.y * u4.y + v.z * u4.z + v.w * u4.w;
        d = warpSum(d);
        if (lane == 0) {
            g_logits[b * M_ + m] = d;
            if (write_out) out[(size_t)b * M_ + m] = d;
        }
    }
}

extern "C" void kernel_launch(void* const* d_in, const int* in_sizes, int n_in,
                              void* d_out, int out_size)
{
    const int*   story  = (const int*)  d_in[0];   // [B, M, S] int32
    const float* hidden = (const float*)d_in[1];   // [B, 1, D] f32
    const float* C      = (const float*)d_in[2];   // [4, V, D] f32
    float* out = (float*)d_out;                    // [B*M] logits ++ [B*D] u

    k_gather <<<(B_ * M_) / 8, 256>>>(story, hidden, C);

    k_combine<<<B_ * NSPL, 256>>>(hidden, out, 0);   // hop 0: u1 = u0 + o0
    k_logits <<<B_ * NSPL, 256>>>(out, 0, 0);        // logits entering hop 1
    k_combine<<<B_ * NSPL, 256>>>(hidden, out, 1);   // hop 1: u2 = u1 + o1
    k_logits <<<B_ * NSPL, 256>>>(out, 1, 1);        // logits entering hop 2 -> OUTPUT
    k_combine<<<B_ * NSPL, 256>>>(hidden, out, 2);   // hop 2: u3 -> OUTPUT
}